// round 17
// baseline (speedup 1.0000x reference)
#include <cuda_runtime.h>
#include <cstdint>

// DepenL via tiled shared-memory formulation (R7 + mixed store policy).
// out1: default write-back stores -> lines stay dirty in L2 and are
// overwritten in place on the next graph replay (never drain to DRAM).
// out2: evict-first streaming stores -> leaves L2 quickly, no thrash.

#define WW   128
#define LL   16384
#define MM   147456   // 9*L
#define HC   16       // rows per block chunk
#define NR   (HC + 4) // stored rows (halo 2 each side)
#define RS   136      // smem row stride (floats); data at col w+4
#define NT   256

__global__ __launch_bounds__(NT)
void depenl_tile(const float* __restrict__ key,
                 const float* __restrict__ query,
                 float* __restrict__ out1,
                 float* __restrict__ out2) {
    __shared__ float sK[NR * RS];
    __shared__ float sQ[NR * RS];

    const int bx    = blockIdx.x;
    const int ch    = bx >> 3;      // 0..255  (B*C)
    const int chunk = bx & 7;       // 0..7
    const int h0    = chunk * HC;
    const int tid   = threadIdx.x;

    const float* __restrict__ kb = key   + (size_t)ch * LL;
    const float* __restrict__ qb = query + (size_t)ch * LL;

    // zero entire smem (covers pad cols, out-of-image halo rows)
    for (int idx = tid; idx < NR * RS; idx += NT) { sK[idx] = 0.f; sQ[idx] = 0.f; }
    __syncthreads();

    // fill valid rows: gh = h0-2+r, cols [4, 132) <- x[gh, 0..127]
    for (int t = tid; t < NR * 32; t += NT) {
        const int r  = t >> 5;
        const int c4 = (t & 31) * 4;
        const int gh = h0 - 2 + r;
        if ((unsigned)gh < 128u) {
            *reinterpret_cast<float4*>(&sK[r * RS + 4 + c4]) =
                *reinterpret_cast<const float4*>(kb + gh * WW + c4);
            *reinterpret_cast<float4*>(&sQ[r * RS + 4 + c4]) =
                *reinterpret_cast<const float4*>(qb + gh * WW + c4);
        }
    }
    __syncthreads();

    const int l0 = h0 * WW;
    float* __restrict__ o1c = out1 + (size_t)ch * MM;
    float* __restrict__ o2c = out2 + (size_t)ch * MM;

    for (int p = 0; p < 9; ++p) {
        const int i = (p * 11) >> 5;     // p/3
        const int j = p - i * 3;         // p%3
        int r = (4 * p + l0 + tid) % 9;  // (4p+l) mod 9, updated incrementally
        int l_loc = tid;                 // l - l0
        float* o1 = o1c + p * LL + l0 + tid;
        float* o2 = o2c + p * LL + l0 + tid;

        #pragma unroll
        for (int it = 0; it < (HC * WW) / NT; ++it) {
            const int h_loc = l_loc >> 7;          // 0..15
            const int w     = l_loc & 127;
            const int nofs  = (h_loc + i + 1) * RS + (w + j + 3);
            const float kn = sK[nofs];
            const float qn = sQ[nofs];

            const int d      = 4 - r;
            const int lc_loc = l_loc + d;          // may be -4..HC*128+3
            const int glc    = l0 + lc_loc;
            float kc, qc;
            if ((unsigned)glc < (unsigned)LL) {
                // same-p center; arithmetic >>/& handle lc_loc<0 correctly
                const int cofs = ((lc_loc >> 7) + i + 1) * RS
                               + ((lc_loc & 127) + j + 3);
                kc = sK[cofs];
                qc = sQ[cofs];
            } else {
                // rare: center falls in adjacent p-plane
                const int m   = p * LL + glc - d;  // p*LL + l
                const int mc  = m + d;
                const int pc  = mc >> 14;
                const int lc2 = mc & 16383;
                const int ic  = (pc * 11) >> 5;
                const int jc  = pc - ic * 3;
                const int hc2 = (lc2 >> 7) + ic - 1;
                const int wc2 = (lc2 & 127) + jc - 1;
                const bool ok = ((unsigned)hc2 < 128u) && ((unsigned)wc2 < 128u);
                const int gi  = (hc2 << 7) + wc2;
                kc = ok ? __ldg(kb + gi) : 0.f;
                qc = ok ? __ldg(qb + gi) : 0.f;
            }

            *o1 = kn * qc;          // write-back: stays L2-resident across replays
            __stcs(o2, kc * qn);    // streaming (evict-first) store

            o1 += NT; o2 += NT;
            l_loc += NT;
            r += 4; if (r >= 9) r -= 9;
        }
    }
}

extern "C" void kernel_launch(void* const* d_in, const int* in_sizes, int n_in,
                              void* d_out, int out_size) {
    const float* key   = (const float*)d_in[0];
    const float* query = (const float*)d_in[1];
    float* out1 = (float*)d_out;
    float* out2 = out1 + (size_t)256 * MM;

    depenl_tile<<<256 * 8, NT>>>(key, query, out1, out2);
}